// round 12
// baseline (speedup 1.0000x reference)
#include <cuda_runtime.h>
#include <cuda_bf16.h>
#include <cuda_fp16.h>
#include <stdint.h>
#include <string.h>
#include <math.h>

#define NN 50000
#define EE 800000
#define ET (EE + NN)
#define HC 256
#define NEG_ATT 0.2f
#define NEG_ACT 0.01f
#define EPSN 1e-5f
#define NBLK 196            // ceil(NN/256)
#define NSTRIPE 32

// ---------------- scratch ----------------
__device__ __align__(16) __half2 g_hh[NN * 128];       // h in fp16 (128 half2 per row)
__device__ __align__(16) float g_o[NN * HC];           // aggregate output (raw, pre-norm)
__device__ __align__(16) float g_s[NN * 4];
__device__ __align__(16) float g_d[NN * 4];
__device__ __align__(16) __nv_bfloat16 g_wh[HC * HC];  // W transposed [n][k], bf16 hi
__device__ __align__(16) __nv_bfloat16 g_wl[HC * HC];  // W transposed [n][k], bf16 lo
__device__ int   g_deg[NN + 1];
__device__ int   g_off[NN + 1];
__device__ int   g_cur[NN];
__device__ int   g_csr[ET];
__device__ int   g_bsum[NBLK];
__device__ int   g_boff[NBLK];
__device__ float g_statsP[3][NSTRIPE][512];            // striped per-layer stats

__device__ __forceinline__ uint32_t smem_u32(const void* p) {
    uint32_t a;
    asm("{ .reg .u64 t; cvta.to.shared.u64 t, %1; cvt.u32.u64 %0, t; }" : "=r"(a) : "l"(p));
    return a;
}
__device__ __forceinline__ uint32_t bf2(float x, float y) {
    __nv_bfloat162 t = __floats2bfloat162_rn(x, y);
    uint32_t r; memcpy(&r, &t, 4); return r;
}
__device__ __forceinline__ void ldm4(uint32_t& r0, uint32_t& r1, uint32_t& r2, uint32_t& r3, uint32_t a) {
    asm volatile("ldmatrix.sync.aligned.m8n8.x4.shared.b16 {%0,%1,%2,%3}, [%4];"
                 : "=r"(r0), "=r"(r1), "=r"(r2), "=r"(r3) : "r"(a));
}
__device__ __forceinline__ void mma16816(float* c, const uint32_t* a, const uint32_t* b) {
    asm volatile("mma.sync.aligned.m16n8k16.row.col.f32.bf16.bf16.f32 "
                 "{%0,%1,%2,%3}, {%4,%5,%6,%7}, {%8,%9}, {%0,%1,%2,%3};"
                 : "+f"(c[0]), "+f"(c[1]), "+f"(c[2]), "+f"(c[3])
                 : "r"(a[0]), "r"(a[1]), "r"(a[2]), "r"(a[3]), "r"(b[0]), "r"(b[1]));
}
__device__ __forceinline__ float lrelu_act(float v) { return v > 0.f ? v : NEG_ACT * v; }
__device__ __forceinline__ float lrelu_att(float v) { return v > 0.f ? v : NEG_ATT * v; }

// ---------------- CSR build (+ stats zeroing) ----------------
__global__ void reset_build_k() {
    int i = blockIdx.x * blockDim.x + threadIdx.x;
    if (i < NN) { g_deg[i] = 0; g_cur[i] = 0; }
    if (i < 3 * NSTRIPE * 512) ((float*)g_statsP)[i] = 0.f;
}
__global__ void hist_k(const int* __restrict__ ei) {
    int i = blockIdx.x * blockDim.x + threadIdx.x;
    if (i >= ET) return;
    int dv = (i < EE) ? ei[EE + i] : (i - EE);
    atomicAdd(&g_deg[dv], 1);
}
// parallel scan: block sums -> tiny scan -> per-block scan+apply
__global__ void scan1_k() {
    __shared__ int sh[256];
    int i = blockIdx.x * 256 + threadIdx.x;
    int v = (i < NN) ? g_deg[i] : 0;
    sh[threadIdx.x] = v;
    __syncthreads();
    for (int d = 128; d; d >>= 1) {
        if (threadIdx.x < d) sh[threadIdx.x] += sh[threadIdx.x + d];
        __syncthreads();
    }
    if (threadIdx.x == 0) g_bsum[blockIdx.x] = sh[0];
}
__global__ void scan2_k() {
    __shared__ int sh[256];
    int t = threadIdx.x;
    sh[t] = (t < NBLK) ? g_bsum[t] : 0;
    __syncthreads();
    for (int d = 1; d < 256; d <<= 1) {
        int v = (t >= d) ? sh[t - d] : 0;
        __syncthreads();
        sh[t] += v;
        __syncthreads();
    }
    if (t < NBLK) g_boff[t] = (t > 0) ? sh[t - 1] : 0;
    if (t == 255) g_off[NN] = sh[255];
}
__global__ void scan3_k() {
    __shared__ int sh[256];
    int i = blockIdx.x * 256 + threadIdx.x;
    int t = threadIdx.x;
    int v = (i < NN) ? g_deg[i] : 0;
    sh[t] = v;
    __syncthreads();
    for (int d = 1; d < 256; d <<= 1) {
        int u = (t >= d) ? sh[t - d] : 0;
        __syncthreads();
        sh[t] += u;
        __syncthreads();
    }
    if (i < NN) g_off[i] = g_boff[blockIdx.x] + sh[t] - v;   // exclusive
}
__global__ void fill_k(const int* __restrict__ ei) {
    int i = blockIdx.x * blockDim.x + threadIdx.x;
    if (i >= ET) return;
    int sv, dv;
    if (i < EE) { sv = ei[i]; dv = ei[EE + i]; }
    else        { sv = dv = i - EE; }
    int p = g_off[dv] + atomicAdd(&g_cur[dv], 1);
    g_csr[p] = sv;
}

// ---------------- W transpose + bf16 hi/lo split ----------------
__global__ void convw_k(const float* __restrict__ W) {
    int i = blockIdx.x * 256 + threadIdx.x;
    int n = i >> 8, k = i & 255;
    float v = W[k * 256 + n];
    __nv_bfloat16 h = __float2bfloat16(v);
    float lo = v - __bfloat162float(h);
    g_wh[n * 256 + k] = h;
    g_wl[n * 256 + k] = __float2bfloat16(lo);
}

// ---------------- HMMA GEMM (R11 winner; norm reads striped stats) ----------------
__global__ __launch_bounds__(256, 2) void gemm_k(const float* __restrict__ A, int norm_layer,
                                                 const float* __restrict__ gw,
                                                 const float* __restrict__ gb,
                                                 const float* __restrict__ ga,
                                                 const float* __restrict__ asrc,
                                                 const float* __restrict__ adst) {
    __shared__ __align__(16) char sm[32768];
    __shared__ float s_scale[256], s_shift[256];
    __shared__ float s_as[128], s_ad[128];
    __shared__ float s_red[128][2][2];
    const uint32_t sAh = smem_u32(sm);
    const uint32_t sAl = sAh + 8192;
    const uint32_t sBh = sAh + 16384;
    const uint32_t sBl = sAh + 24576;
    char* cAh = sm; char* cAl = sm + 8192; char* cBh = sm + 16384; char* cBl = sm + 24576;

    const int tid  = threadIdx.x;
    const int wid  = tid >> 5;
    const int lane = tid & 31;
    const int bm = blockIdx.x * 128;
    const int n0 = blockIdx.y * 128;
    const int m_off = (wid >> 2) * 64;
    const int n_off = (wid & 3) * 32;

    const int use_norm = (norm_layer >= 0);
    if (use_norm) {
        int c = tid;
        float s = 0.f, s2 = 0.f;
#pragma unroll
        for (int k = 0; k < NSTRIPE; k++) {
            s  += g_statsP[norm_layer][k][c];
            s2 += g_statsP[norm_layer][k][256 + c];
        }
        float mu  = s * (1.f / NN);
        float ex2 = s2 * (1.f / NN);
        float a = ga[c];
        float var = ex2 - 2.f * a * mu * mu + a * a * mu * mu;
        float sc = gw[c] * rsqrtf(var + EPSN);
        s_scale[c] = sc;
        s_shift[c] = gb[c] - a * mu * sc;
    } else {
        s_scale[tid] = 1.f;
        s_shift[tid] = 0.f;
    }
    if (tid < 128) {
        s_as[tid] = asrc[n0 + tid];
        s_ad[tid] = adst[n0 + tid];
    }
    {
        float* z = &s_red[0][0][0];
        z[tid] = 0.f;
        z[tid + 256] = 0.f;
    }
    __syncthreads();

    float acc[4][4][4];
#pragma unroll
    for (int i = 0; i < 4; i++)
#pragma unroll
        for (int j = 0; j < 4; j++)
#pragma unroll
            for (int r = 0; r < 4; r++) acc[i][j][r] = 0.f;

    for (int c = 0; c < 8; c++) {
        const int k0 = c * 32;
#pragma unroll
        for (int it = 0; it < 2; it++) {
            int slot = tid + it * 256;
            int row = slot >> 2, cc = slot & 3;
            float4 v0 = make_float4(0.f, 0.f, 0.f, 0.f), v1 = v0;
            if (bm + row < NN) {
                const float* p = A + (size_t)(bm + row) * 256 + k0 + cc * 8;
                v0 = *(const float4*)p;
                v1 = *(const float4*)(p + 4);
            }
            if (use_norm) {
                int cb = k0 + cc * 8;
                v0.x = lrelu_act(s_scale[cb + 0] * v0.x + s_shift[cb + 0]);
                v0.y = lrelu_act(s_scale[cb + 1] * v0.y + s_shift[cb + 1]);
                v0.z = lrelu_act(s_scale[cb + 2] * v0.z + s_shift[cb + 2]);
                v0.w = lrelu_act(s_scale[cb + 3] * v0.w + s_shift[cb + 3]);
                v1.x = lrelu_act(s_scale[cb + 4] * v1.x + s_shift[cb + 4]);
                v1.y = lrelu_act(s_scale[cb + 5] * v1.y + s_shift[cb + 5]);
                v1.z = lrelu_act(s_scale[cb + 6] * v1.z + s_shift[cb + 6]);
                v1.w = lrelu_act(s_scale[cb + 7] * v1.w + s_shift[cb + 7]);
            }
            uint4 hi, lo;
            hi.x = bf2(v0.x, v0.y); hi.y = bf2(v0.z, v0.w);
            hi.z = bf2(v1.x, v1.y); hi.w = bf2(v1.z, v1.w);
            __nv_bfloat162 t;
            memcpy(&t, &hi.x, 4);
            lo.x = bf2(v0.x - __bfloat162float(t.x), v0.y - __bfloat162float(t.y));
            memcpy(&t, &hi.y, 4);
            lo.y = bf2(v0.z - __bfloat162float(t.x), v0.w - __bfloat162float(t.y));
            memcpy(&t, &hi.z, 4);
            lo.z = bf2(v1.x - __bfloat162float(t.x), v1.y - __bfloat162float(t.y));
            memcpy(&t, &hi.w, 4);
            lo.w = bf2(v1.z - __bfloat162float(t.x), v1.w - __bfloat162float(t.y));
            int off = row * 64 + ((cc ^ (row & 3)) << 4);
            *(uint4*)(cAh + off) = hi;
            *(uint4*)(cAl + off) = lo;
        }
#pragma unroll
        for (int it = 0; it < 2; it++) {
            int slot = tid + it * 256;
            int row = slot >> 2, cc = slot & 3;
            size_t go = (size_t)(n0 + row) * 256 + k0 + cc * 8;
            int off = row * 64 + ((cc ^ (row & 3)) << 4);
            *(uint4*)(cBh + off) = *(const uint4*)(g_wh + go);
            *(uint4*)(cBl + off) = *(const uint4*)(g_wl + go);
        }
        __syncthreads();

#pragma unroll
        for (int kk2 = 0; kk2 < 2; kk2++) {
            uint32_t afh[4][4], afl[4][4], bfh[4][2], bfl[4][2];
#pragma unroll
            for (int mi = 0; mi < 4; mi++) {
                int row_a = m_off + mi * 16 + (lane & 15);
                int cc_a = kk2 * 2 + (lane >> 4);
                uint32_t off = (uint32_t)(row_a * 64 + ((cc_a ^ (row_a & 3)) << 4));
                ldm4(afh[mi][0], afh[mi][1], afh[mi][2], afh[mi][3], sAh + off);
                ldm4(afl[mi][0], afl[mi][1], afl[mi][2], afl[mi][3], sAl + off);
            }
#pragma unroll
            for (int p = 0; p < 2; p++) {
                int gq = lane >> 3;
                int row_b = n_off + p * 16 + ((gq >> 1) << 3) + (lane & 7);
                int cc_b = kk2 * 2 + (gq & 1);
                uint32_t off = (uint32_t)(row_b * 64 + ((cc_b ^ (row_b & 3)) << 4));
                ldm4(bfh[2 * p][0], bfh[2 * p][1], bfh[2 * p + 1][0], bfh[2 * p + 1][1], sBh + off);
                ldm4(bfl[2 * p][0], bfl[2 * p][1], bfl[2 * p + 1][0], bfl[2 * p + 1][1], sBl + off);
            }
#pragma unroll
            for (int mi = 0; mi < 4; mi++)
#pragma unroll
                for (int nj = 0; nj < 4; nj++) {
                    mma16816(acc[mi][nj], afh[mi], bfh[nj]);
                    mma16816(acc[mi][nj], afh[mi], bfl[nj]);
                    mma16816(acc[mi][nj], afl[mi], bfh[nj]);
                }
        }
        __syncthreads();
    }

    // ---- epilogue: fp16 store + fused s/d (fp32 acc) ----
    const int hl = n_off >> 6;
#pragma unroll
    for (int mi = 0; mi < 4; mi++) {
        int r0 = m_off + mi * 16 + (lane >> 2);
        int m_g = bm + r0;
        float sS0 = 0.f, sS1 = 0.f, sD0 = 0.f, sD1 = 0.f;
#pragma unroll
        for (int nj = 0; nj < 4; nj++) {
            int cl = n_off + nj * 8 + (lane & 3) * 2;
            int n_g = n0 + cl;
            float a0 = s_as[cl], a1 = s_as[cl + 1];
            float d0 = s_ad[cl], d1 = s_ad[cl + 1];
            sS0 += acc[mi][nj][0] * a0 + acc[mi][nj][1] * a1;
            sD0 += acc[mi][nj][0] * d0 + acc[mi][nj][1] * d1;
            sS1 += acc[mi][nj][2] * a0 + acc[mi][nj][3] * a1;
            sD1 += acc[mi][nj][2] * d0 + acc[mi][nj][3] * d1;
            if (m_g < NN)
                g_hh[(size_t)m_g * 128 + (n_g >> 1)] = __floats2half2_rn(acc[mi][nj][0], acc[mi][nj][1]);
            if (m_g + 8 < NN)
                g_hh[(size_t)(m_g + 8) * 128 + (n_g >> 1)] = __floats2half2_rn(acc[mi][nj][2], acc[mi][nj][3]);
        }
#pragma unroll
        for (int o = 1; o < 4; o <<= 1) {
            sS0 += __shfl_xor_sync(0xffffffffu, sS0, o);
            sS1 += __shfl_xor_sync(0xffffffffu, sS1, o);
            sD0 += __shfl_xor_sync(0xffffffffu, sD0, o);
            sD1 += __shfl_xor_sync(0xffffffffu, sD1, o);
        }
        if ((lane & 3) == 0) {
            atomicAdd(&s_red[r0][hl][0], sS0);
            atomicAdd(&s_red[r0][hl][1], sD0);
            atomicAdd(&s_red[r0 + 8][hl][0], sS1);
            atomicAdd(&s_red[r0 + 8][hl][1], sD1);
        }
    }
    __syncthreads();
    {
        const int hbase = (n0 >> 6);
        int i = tid;
        int row = i >> 1, h2 = i & 1;
        if (bm + row < NN) {
            g_s[(size_t)(bm + row) * 4 + hbase + h2] = s_red[row][h2][0];
            g_d[(size_t)(bm + row) * 4 + hbase + h2] = s_red[row][h2][1];
        }
    }
}

// ---------------- GAT aggregation + fused striped stats ----------------
// grid must be exactly NN*32/256 = 6250 blocks (NN divisible by 8).
__global__ void agg_k(const float* __restrict__ bias, int concat, int layer) {
    __shared__ float ssum[256], ssq[256];
    const int tid = threadIdx.x;
    ssum[tid] = 0.f;
    ssq[tid] = 0.f;
    __syncthreads();

    int w = (blockIdx.x * blockDim.x + tid) >> 5;
    int lane = tid & 31;

    const int mh = lane >> 3;
    float dhm = g_d[w * 4 + mh];
    int jb = g_off[w], je = g_off[w + 1];

    float acc[8] = {0.f, 0.f, 0.f, 0.f, 0.f, 0.f, 0.f, 0.f};
    float den = 0.f;
    for (int j = jb; j < je; j++) {
        int sr = g_csr[j];
        float e = lrelu_att(g_s[sr * 4 + mh] + dhm);
        float wv = __expf(e);
        den += wv;
        uint4 hv = *((const uint4*)(g_hh + (size_t)sr * 128) + lane);
        float2 f0 = __half22float2(*(__half2*)&hv.x);
        float2 f1 = __half22float2(*(__half2*)&hv.y);
        float2 f2 = __half22float2(*(__half2*)&hv.z);
        float2 f3 = __half22float2(*(__half2*)&hv.w);
        acc[0] += wv * f0.x; acc[1] += wv * f0.y;
        acc[2] += wv * f1.x; acc[3] += wv * f1.y;
        acc[4] += wv * f2.x; acc[5] += wv * f2.y;
        acc[6] += wv * f3.x; acc[7] += wv * f3.y;
    }
    float invd = 1.f / den;

    if (concat) {
        int c0 = 8 * lane;
        float o[8];
#pragma unroll
        for (int i = 0; i < 8; i++) o[i] = acc[i] * invd + bias[c0 + i];
        *(float4*)(g_o + (size_t)w * 256 + c0)     = make_float4(o[0], o[1], o[2], o[3]);
        *(float4*)(g_o + (size_t)w * 256 + c0 + 4) = make_float4(o[4], o[5], o[6], o[7]);
#pragma unroll
        for (int i = 0; i < 8; i++) {
            atomicAdd(&ssum[c0 + i], o[i]);
            atomicAdd(&ssq[c0 + i], o[i] * o[i]);
        }
    } else {
        float v[8];
#pragma unroll
        for (int i = 0; i < 8; i++) {
            float r = acc[i] * invd;
            r += __shfl_xor_sync(0xffffffffu, r, 8);
            r += __shfl_xor_sync(0xffffffffu, r, 16);
            v[i] = 0.25f * r;
        }
        if (lane < 8) {
            int cc = 8 * lane;
            float o[8];
#pragma unroll
            for (int i = 0; i < 8; i++) o[i] = v[i] + bias[cc + i];
            *(float4*)(g_o + (size_t)w * 64 + cc)     = make_float4(o[0], o[1], o[2], o[3]);
            *(float4*)(g_o + (size_t)w * 64 + cc + 4) = make_float4(o[4], o[5], o[6], o[7]);
#pragma unroll
            for (int i = 0; i < 8; i++) {
                atomicAdd(&ssum[cc + i], o[i]);
                atomicAdd(&ssq[cc + i], o[i] * o[i]);
            }
        }
    }
    __syncthreads();
    float* gp = g_statsP[layer][blockIdx.x & (NSTRIPE - 1)];
    int C = concat ? 256 : 64;
    if (tid < C) {
        atomicAdd(gp + tid, ssum[tid]);
        atomicAdd(gp + 256 + tid, ssq[tid]);
    }
}

// ---------------- MLP head with fused GraphNorm+LeakyReLU on input ----------------
__global__ __launch_bounds__(128) void mlp_k(const float* __restrict__ mW0, const float* __restrict__ mb0,
                                             const float* __restrict__ mW1, const float* __restrict__ mb1,
                                             const float* __restrict__ mW2, const float* __restrict__ mb2,
                                             const float* __restrict__ gw, const float* __restrict__ gb,
                                             const float* __restrict__ ga,
                                             float* __restrict__ out) {
    __shared__ float w0[64 * 32], w1[32 * 16], w2[16 * 2], bb0[32], bb1[16], bb2[2];
    __shared__ float s_scale[64], s_shift[64];
    int t = threadIdx.x;
    for (int i = t; i < 64 * 32; i += blockDim.x) w0[i] = mW0[i];
    for (int i = t; i < 32 * 16; i += blockDim.x) w1[i] = mW1[i];
    for (int i = t; i < 16 * 2;  i += blockDim.x) w2[i] = mW2[i];
    if (t < 32) bb0[t] = mb0[t];
    if (t < 16) bb1[t] = mb1[t];
    if (t < 2)  bb2[t] = mb2[t];
    if (t < 64) {
        float s = 0.f, s2 = 0.f;
#pragma unroll
        for (int k = 0; k < NSTRIPE; k++) {
            s  += g_statsP[2][k][t];
            s2 += g_statsP[2][k][256 + t];
        }
        float mu  = s * (1.f / NN);
        float ex2 = s2 * (1.f / NN);
        float a = ga[t];
        float var = ex2 - 2.f * a * mu * mu + a * a * mu * mu;
        float sc = gw[t] * rsqrtf(var + EPSN);
        s_scale[t] = sc;
        s_shift[t] = gb[t] - a * mu * sc;
    }
    __syncthreads();
    int n = blockIdx.x * blockDim.x + t;
    if (n >= NN) return;
    float in[64];
#pragma unroll
    for (int k = 0; k < 64; k++)
        in[k] = lrelu_act(s_scale[k] * g_o[(size_t)n * 64 + k] + s_shift[k]);
    float h1[32];
#pragma unroll
    for (int j = 0; j < 32; j++) {
        float s = bb0[j];
#pragma unroll
        for (int k = 0; k < 64; k++) s += in[k] * w0[k * 32 + j];
        h1[j] = fmaxf(s, 0.f);
    }
    float h2[16];
#pragma unroll
    for (int j = 0; j < 16; j++) {
        float s = bb1[j];
#pragma unroll
        for (int k = 0; k < 32; k++) s += h1[k] * w1[k * 16 + j];
        h2[j] = fmaxf(s, 0.f);
    }
    float o0 = bb2[0], o1 = bb2[1];
#pragma unroll
    for (int k = 0; k < 16; k++) { o0 += h2[k] * w2[k * 2]; o1 += h2[k] * w2[k * 2 + 1]; }
    out[(size_t)n * 2]     = o0;
    out[(size_t)n * 2 + 1] = o1;
}

// ---------------- launch ----------------
extern "C" void kernel_launch(void* const* d_in, const int* in_sizes, int n_in,
                              void* d_out, int out_size) {
    const float* x  = (const float*)d_in[0];
    const int*   ei = (const int*)d_in[1];
    const float* W[3]  = {(const float*)d_in[2],  (const float*)d_in[9],  (const float*)d_in[16]};
    const float* As[3] = {(const float*)d_in[3],  (const float*)d_in[10], (const float*)d_in[17]};
    const float* Ad[3] = {(const float*)d_in[4],  (const float*)d_in[11], (const float*)d_in[18]};
    const float* Bb[3] = {(const float*)d_in[5],  (const float*)d_in[12], (const float*)d_in[19]};
    const float* Gw[3] = {(const float*)d_in[6],  (const float*)d_in[13], (const float*)d_in[20]};
    const float* Gb[3] = {(const float*)d_in[7],  (const float*)d_in[14], (const float*)d_in[21]};
    const float* Ga[3] = {(const float*)d_in[8],  (const float*)d_in[15], (const float*)d_in[22]};
    const float* mW0 = (const float*)d_in[23];
    const float* mb0 = (const float*)d_in[24];
    const float* mW1 = (const float*)d_in[25];
    const float* mb1 = (const float*)d_in[26];
    const float* mW2 = (const float*)d_in[27];
    const float* mb2 = (const float*)d_in[28];

    void* p_o = nullptr;
    cudaGetSymbolAddress(&p_o, g_o);

    // CSR build + stats zeroing (parallel scan)
    reset_build_k<<<NBLK, 256>>>();
    hist_k<<<(ET + 255) / 256, 256>>>(ei);
    scan1_k<<<NBLK, 256>>>();
    scan2_k<<<1, 256>>>();
    scan3_k<<<NBLK, 256>>>();
    fill_k<<<(ET + 255) / 256, 256>>>(ei);

    const float* cur_in = x;
    for (int l = 0; l < 3; l++) {
        convw_k<<<256, 256>>>(W[l]);
        dim3 gg((NN + 127) / 128, 2);
        int pn = (l > 0) ? (l - 1) : 0;
        gemm_k<<<gg, 256>>>(cur_in, l - 1, Gw[pn], Gb[pn], Ga[pn], As[l], Ad[l]);
        agg_k<<<NN * 32 / 256, 256>>>(Bb[l], (l < 2) ? 1 : 0, l);
        cur_in = (const float*)p_o;
    }
    mlp_k<<<(NN + 127) / 128, 128>>>(mW0, mb0, mW1, mb1, mW2, mb2,
                                     Gw[2], Gb[2], Ga[2], (float*)d_out);
}

// round 13
// speedup vs baseline: 1.2613x; 1.2613x over previous
#include <cuda_runtime.h>
#include <cuda_bf16.h>
#include <cuda_fp16.h>
#include <stdint.h>
#include <string.h>
#include <math.h>

#define NN 50000
#define EE 800000
#define ET (EE + NN)
#define HC 256
#define NEG_ATT 0.2f
#define NEG_ACT 0.01f
#define EPSN 1e-5f
#define NBLK 196            // ceil(NN/256)

// ---------------- scratch ----------------
__device__ __align__(16) __half2 g_hh[NN * 128];       // h in fp16 (128 half2 per row)
__device__ __align__(16) float g_o[NN * HC];           // aggregate output (raw, pre-norm)
__device__ __align__(16) float g_s[NN * 4];
__device__ __align__(16) float g_d[NN * 4];
__device__ __align__(16) __nv_bfloat16 g_wh[HC * HC];  // W transposed [n][k], bf16 hi
__device__ __align__(16) __nv_bfloat16 g_wl[HC * HC];  // W transposed [n][k], bf16 lo
__device__ int   g_deg[NN + 1];
__device__ int   g_off[NN + 1];
__device__ int   g_cur[NN];
__device__ int   g_csr[ET];
__device__ int   g_bsum[NBLK];
__device__ int   g_boff[NBLK];
__device__ float g_stats3[3][512];                     // per layer: [0:256) sum, [256:512) sumsq

__device__ __forceinline__ uint32_t smem_u32(const void* p) {
    uint32_t a;
    asm("{ .reg .u64 t; cvta.to.shared.u64 t, %1; cvt.u32.u64 %0, t; }" : "=r"(a) : "l"(p));
    return a;
}
__device__ __forceinline__ uint32_t bf2(float x, float y) {
    __nv_bfloat162 t = __floats2bfloat162_rn(x, y);
    uint32_t r; memcpy(&r, &t, 4); return r;
}
__device__ __forceinline__ void ldm4(uint32_t& r0, uint32_t& r1, uint32_t& r2, uint32_t& r3, uint32_t a) {
    asm volatile("ldmatrix.sync.aligned.m8n8.x4.shared.b16 {%0,%1,%2,%3}, [%4];"
                 : "=r"(r0), "=r"(r1), "=r"(r2), "=r"(r3) : "r"(a));
}
__device__ __forceinline__ void mma16816(float* c, const uint32_t* a, const uint32_t* b) {
    asm volatile("mma.sync.aligned.m16n8k16.row.col.f32.bf16.bf16.f32 "
                 "{%0,%1,%2,%3}, {%4,%5,%6,%7}, {%8,%9}, {%0,%1,%2,%3};"
                 : "+f"(c[0]), "+f"(c[1]), "+f"(c[2]), "+f"(c[3])
                 : "r"(a[0]), "r"(a[1]), "r"(a[2]), "r"(a[3]), "r"(b[0]), "r"(b[1]));
}
__device__ __forceinline__ float lrelu_act(float v) { return v > 0.f ? v : NEG_ACT * v; }
__device__ __forceinline__ float lrelu_att(float v) { return v > 0.f ? v : NEG_ATT * v; }

// ---------------- CSR build (+ per-layer stats zeroing) ----------------
__global__ void reset_build_k() {
    int i = blockIdx.x * blockDim.x + threadIdx.x;
    if (i < NN) { g_deg[i] = 0; g_cur[i] = 0; }
    if (i < 1536) ((float*)g_stats3)[i] = 0.f;
}
__global__ void hist_k(const int* __restrict__ ei) {
    int i = blockIdx.x * blockDim.x + threadIdx.x;
    if (i >= ET) return;
    int dv = (i < EE) ? ei[EE + i] : (i - EE);
    atomicAdd(&g_deg[dv], 1);
}
// parallel scan: block sums -> tiny scan -> per-block scan+apply
__global__ void scan1_k() {
    __shared__ int sh[256];
    int i = blockIdx.x * 256 + threadIdx.x;
    int v = (i < NN) ? g_deg[i] : 0;
    sh[threadIdx.x] = v;
    __syncthreads();
    for (int d = 128; d; d >>= 1) {
        if (threadIdx.x < d) sh[threadIdx.x] += sh[threadIdx.x + d];
        __syncthreads();
    }
    if (threadIdx.x == 0) g_bsum[blockIdx.x] = sh[0];
}
__global__ void scan2_k() {
    __shared__ int sh[256];
    int t = threadIdx.x;
    sh[t] = (t < NBLK) ? g_bsum[t] : 0;
    __syncthreads();
    for (int d = 1; d < 256; d <<= 1) {
        int v = (t >= d) ? sh[t - d] : 0;
        __syncthreads();
        sh[t] += v;
        __syncthreads();
    }
    if (t < NBLK) g_boff[t] = (t > 0) ? sh[t - 1] : 0;
    if (t == 255) g_off[NN] = sh[255];
}
__global__ void scan3_k() {
    __shared__ int sh[256];
    int i = blockIdx.x * 256 + threadIdx.x;
    int t = threadIdx.x;
    int v = (i < NN) ? g_deg[i] : 0;
    sh[t] = v;
    __syncthreads();
    for (int d = 1; d < 256; d <<= 1) {
        int u = (t >= d) ? sh[t - d] : 0;
        __syncthreads();
        sh[t] += u;
        __syncthreads();
    }
    if (i < NN) g_off[i] = g_boff[blockIdx.x] + sh[t] - v;   // exclusive
}
__global__ void fill_k(const int* __restrict__ ei) {
    int i = blockIdx.x * blockDim.x + threadIdx.x;
    if (i >= ET) return;
    int sv, dv;
    if (i < EE) { sv = ei[i]; dv = ei[EE + i]; }
    else        { sv = dv = i - EE; }
    int p = g_off[dv] + atomicAdd(&g_cur[dv], 1);
    g_csr[p] = sv;
}

// ---------------- W transpose + bf16 hi/lo split ----------------
__global__ void convw_k(const float* __restrict__ W) {
    int i = blockIdx.x * 256 + threadIdx.x;
    int n = i >> 8, k = i & 255;
    float v = W[k * 256 + n];
    __nv_bfloat16 h = __float2bfloat16(v);
    float lo = v - __bfloat162float(h);
    g_wh[n * 256 + k] = h;
    g_wl[n * 256 + k] = __float2bfloat16(lo);
}

// ---------------- HMMA GEMM (R11 champion, unchanged) ----------------
__global__ __launch_bounds__(256, 2) void gemm_k(const float* __restrict__ A, int norm_layer,
                                                 const float* __restrict__ gw,
                                                 const float* __restrict__ gb,
                                                 const float* __restrict__ ga,
                                                 const float* __restrict__ asrc,
                                                 const float* __restrict__ adst) {
    __shared__ __align__(16) char sm[32768];
    __shared__ float s_scale[256], s_shift[256];
    __shared__ float s_as[128], s_ad[128];
    __shared__ float s_red[128][2][2];
    const uint32_t sAh = smem_u32(sm);
    const uint32_t sAl = sAh + 8192;
    const uint32_t sBh = sAh + 16384;
    const uint32_t sBl = sAh + 24576;
    char* cAh = sm; char* cAl = sm + 8192; char* cBh = sm + 16384; char* cBl = sm + 24576;

    const int tid  = threadIdx.x;
    const int wid  = tid >> 5;
    const int lane = tid & 31;
    const int bm = blockIdx.x * 128;
    const int n0 = blockIdx.y * 128;
    const int m_off = (wid >> 2) * 64;
    const int n_off = (wid & 3) * 32;

    const int use_norm = (norm_layer >= 0);
    if (use_norm) {
        const float* gs = g_stats3[norm_layer];
        int c = tid;
        float mu  = gs[c] * (1.f / NN);
        float ex2 = gs[256 + c] * (1.f / NN);
        float a = ga[c];
        float var = ex2 - 2.f * a * mu * mu + a * a * mu * mu;
        float sc = gw[c] * rsqrtf(var + EPSN);
        s_scale[c] = sc;
        s_shift[c] = gb[c] - a * mu * sc;
    } else {
        s_scale[tid] = 1.f;
        s_shift[tid] = 0.f;
    }
    if (tid < 128) {
        s_as[tid] = asrc[n0 + tid];
        s_ad[tid] = adst[n0 + tid];
    }
    {
        float* z = &s_red[0][0][0];
        z[tid] = 0.f;
        z[tid + 256] = 0.f;
    }
    __syncthreads();

    float acc[4][4][4];
#pragma unroll
    for (int i = 0; i < 4; i++)
#pragma unroll
        for (int j = 0; j < 4; j++)
#pragma unroll
            for (int r = 0; r < 4; r++) acc[i][j][r] = 0.f;

    for (int c = 0; c < 8; c++) {
        const int k0 = c * 32;
#pragma unroll
        for (int it = 0; it < 2; it++) {
            int slot = tid + it * 256;
            int row = slot >> 2, cc = slot & 3;
            float4 v0 = make_float4(0.f, 0.f, 0.f, 0.f), v1 = v0;
            if (bm + row < NN) {
                const float* p = A + (size_t)(bm + row) * 256 + k0 + cc * 8;
                v0 = *(const float4*)p;
                v1 = *(const float4*)(p + 4);
            }
            if (use_norm) {
                int cb = k0 + cc * 8;
                v0.x = lrelu_act(s_scale[cb + 0] * v0.x + s_shift[cb + 0]);
                v0.y = lrelu_act(s_scale[cb + 1] * v0.y + s_shift[cb + 1]);
                v0.z = lrelu_act(s_scale[cb + 2] * v0.z + s_shift[cb + 2]);
                v0.w = lrelu_act(s_scale[cb + 3] * v0.w + s_shift[cb + 3]);
                v1.x = lrelu_act(s_scale[cb + 4] * v1.x + s_shift[cb + 4]);
                v1.y = lrelu_act(s_scale[cb + 5] * v1.y + s_shift[cb + 5]);
                v1.z = lrelu_act(s_scale[cb + 6] * v1.z + s_shift[cb + 6]);
                v1.w = lrelu_act(s_scale[cb + 7] * v1.w + s_shift[cb + 7]);
            }
            uint4 hi, lo;
            hi.x = bf2(v0.x, v0.y); hi.y = bf2(v0.z, v0.w);
            hi.z = bf2(v1.x, v1.y); hi.w = bf2(v1.z, v1.w);
            __nv_bfloat162 t;
            memcpy(&t, &hi.x, 4);
            lo.x = bf2(v0.x - __bfloat162float(t.x), v0.y - __bfloat162float(t.y));
            memcpy(&t, &hi.y, 4);
            lo.y = bf2(v0.z - __bfloat162float(t.x), v0.w - __bfloat162float(t.y));
            memcpy(&t, &hi.z, 4);
            lo.z = bf2(v1.x - __bfloat162float(t.x), v1.y - __bfloat162float(t.y));
            memcpy(&t, &hi.w, 4);
            lo.w = bf2(v1.z - __bfloat162float(t.x), v1.w - __bfloat162float(t.y));
            int off = row * 64 + ((cc ^ (row & 3)) << 4);
            *(uint4*)(cAh + off) = hi;
            *(uint4*)(cAl + off) = lo;
        }
#pragma unroll
        for (int it = 0; it < 2; it++) {
            int slot = tid + it * 256;
            int row = slot >> 2, cc = slot & 3;
            size_t go = (size_t)(n0 + row) * 256 + k0 + cc * 8;
            int off = row * 64 + ((cc ^ (row & 3)) << 4);
            *(uint4*)(cBh + off) = *(const uint4*)(g_wh + go);
            *(uint4*)(cBl + off) = *(const uint4*)(g_wl + go);
        }
        __syncthreads();

#pragma unroll
        for (int kk2 = 0; kk2 < 2; kk2++) {
            uint32_t afh[4][4], afl[4][4], bfh[4][2], bfl[4][2];
#pragma unroll
            for (int mi = 0; mi < 4; mi++) {
                int row_a = m_off + mi * 16 + (lane & 15);
                int cc_a = kk2 * 2 + (lane >> 4);
                uint32_t off = (uint32_t)(row_a * 64 + ((cc_a ^ (row_a & 3)) << 4));
                ldm4(afh[mi][0], afh[mi][1], afh[mi][2], afh[mi][3], sAh + off);
                ldm4(afl[mi][0], afl[mi][1], afl[mi][2], afl[mi][3], sAl + off);
            }
#pragma unroll
            for (int p = 0; p < 2; p++) {
                int gq = lane >> 3;
                int row_b = n_off + p * 16 + ((gq >> 1) << 3) + (lane & 7);
                int cc_b = kk2 * 2 + (gq & 1);
                uint32_t off = (uint32_t)(row_b * 64 + ((cc_b ^ (row_b & 3)) << 4));
                ldm4(bfh[2 * p][0], bfh[2 * p][1], bfh[2 * p + 1][0], bfh[2 * p + 1][1], sBh + off);
                ldm4(bfl[2 * p][0], bfl[2 * p][1], bfl[2 * p + 1][0], bfl[2 * p + 1][1], sBl + off);
            }
#pragma unroll
            for (int mi = 0; mi < 4; mi++)
#pragma unroll
                for (int nj = 0; nj < 4; nj++) {
                    mma16816(acc[mi][nj], afh[mi], bfh[nj]);
                    mma16816(acc[mi][nj], afh[mi], bfl[nj]);
                    mma16816(acc[mi][nj], afl[mi], bfh[nj]);
                }
        }
        __syncthreads();
    }

    // ---- epilogue: fp16 store + fused s/d (fp32 acc) ----
    const int hl = n_off >> 6;
#pragma unroll
    for (int mi = 0; mi < 4; mi++) {
        int r0 = m_off + mi * 16 + (lane >> 2);
        int m_g = bm + r0;
        float sS0 = 0.f, sS1 = 0.f, sD0 = 0.f, sD1 = 0.f;
#pragma unroll
        for (int nj = 0; nj < 4; nj++) {
            int cl = n_off + nj * 8 + (lane & 3) * 2;
            int n_g = n0 + cl;
            float a0 = s_as[cl], a1 = s_as[cl + 1];
            float d0 = s_ad[cl], d1 = s_ad[cl + 1];
            sS0 += acc[mi][nj][0] * a0 + acc[mi][nj][1] * a1;
            sD0 += acc[mi][nj][0] * d0 + acc[mi][nj][1] * d1;
            sS1 += acc[mi][nj][2] * a0 + acc[mi][nj][3] * a1;
            sD1 += acc[mi][nj][2] * d0 + acc[mi][nj][3] * d1;
            if (m_g < NN)
                g_hh[(size_t)m_g * 128 + (n_g >> 1)] = __floats2half2_rn(acc[mi][nj][0], acc[mi][nj][1]);
            if (m_g + 8 < NN)
                g_hh[(size_t)(m_g + 8) * 128 + (n_g >> 1)] = __floats2half2_rn(acc[mi][nj][2], acc[mi][nj][3]);
        }
#pragma unroll
        for (int o = 1; o < 4; o <<= 1) {
            sS0 += __shfl_xor_sync(0xffffffffu, sS0, o);
            sS1 += __shfl_xor_sync(0xffffffffu, sS1, o);
            sD0 += __shfl_xor_sync(0xffffffffu, sD0, o);
            sD1 += __shfl_xor_sync(0xffffffffu, sD1, o);
        }
        if ((lane & 3) == 0) {
            atomicAdd(&s_red[r0][hl][0], sS0);
            atomicAdd(&s_red[r0][hl][1], sD0);
            atomicAdd(&s_red[r0 + 8][hl][0], sS1);
            atomicAdd(&s_red[r0 + 8][hl][1], sD1);
        }
    }
    __syncthreads();
    {
        const int hbase = (n0 >> 6);
        int i = tid;
        int row = i >> 1, h2 = i & 1;
        if (bm + row < NN) {
            g_s[(size_t)(bm + row) * 4 + hbase + h2] = s_red[row][h2][0];
            g_d[(size_t)(bm + row) * 4 + hbase + h2] = s_red[row][h2][1];
        }
    }
}

// ---------------- GAT aggregation: warp per dst, blocked channel layout (R11) ----------------
__global__ void agg_k(const float* __restrict__ bias, int concat) {
    int w = (blockIdx.x * blockDim.x + threadIdx.x) >> 5;
    int lane = threadIdx.x & 31;
    if (w >= NN) return;

    const int mh = lane >> 3;                 // my head
    float dhm = g_d[w * 4 + mh];
    int jb = g_off[w], je = g_off[w + 1];

    float acc[8] = {0.f, 0.f, 0.f, 0.f, 0.f, 0.f, 0.f, 0.f};
    float den = 0.f;
    for (int j = jb; j < je; j++) {
        int sr = g_csr[j];
        float e = lrelu_att(g_s[sr * 4 + mh] + dhm);
        float wv = __expf(e);
        den += wv;
        uint4 hv = *((const uint4*)(g_hh + (size_t)sr * 128) + lane);
        float2 f0 = __half22float2(*(__half2*)&hv.x);
        float2 f1 = __half22float2(*(__half2*)&hv.y);
        float2 f2 = __half22float2(*(__half2*)&hv.z);
        float2 f3 = __half22float2(*(__half2*)&hv.w);
        acc[0] += wv * f0.x; acc[1] += wv * f0.y;
        acc[2] += wv * f1.x; acc[3] += wv * f1.y;
        acc[4] += wv * f2.x; acc[5] += wv * f2.y;
        acc[6] += wv * f3.x; acc[7] += wv * f3.y;
    }
    float invd = 1.f / den;

    if (concat) {
        int c0 = 8 * lane;
        float4 o0 = make_float4(acc[0] * invd + bias[c0 + 0], acc[1] * invd + bias[c0 + 1],
                                acc[2] * invd + bias[c0 + 2], acc[3] * invd + bias[c0 + 3]);
        float4 o1 = make_float4(acc[4] * invd + bias[c0 + 4], acc[5] * invd + bias[c0 + 5],
                                acc[6] * invd + bias[c0 + 6], acc[7] * invd + bias[c0 + 7]);
        *(float4*)(g_o + (size_t)w * 256 + c0)     = o0;
        *(float4*)(g_o + (size_t)w * 256 + c0 + 4) = o1;
    } else {
        float v[8];
#pragma unroll
        for (int i = 0; i < 8; i++) {
            float r = acc[i] * invd;
            r += __shfl_xor_sync(0xffffffffu, r, 8);
            r += __shfl_xor_sync(0xffffffffu, r, 16);
            v[i] = 0.25f * r;
        }
        if (lane < 8) {
            int cc = 8 * lane;
            float4 o0 = make_float4(v[0] + bias[cc + 0], v[1] + bias[cc + 1],
                                    v[2] + bias[cc + 2], v[3] + bias[cc + 3]);
            float4 o1 = make_float4(v[4] + bias[cc + 4], v[5] + bias[cc + 5],
                                    v[6] + bias[cc + 6], v[7] + bias[cc + 7]);
            *(float4*)(g_o + (size_t)w * 64 + cc)     = o0;
            *(float4*)(g_o + (size_t)w * 64 + cc + 4) = o1;
        }
    }
}

// ---------------- GraphNorm stats (per-layer buffer) ----------------
__global__ void stats_k(int C, int layer) {
    int c = threadIdx.x;
    int r0 = blockIdx.x * 128;
    int re = min(r0 + 128, NN);
    float s = 0.f, s2 = 0.f;
    for (int r = r0; r < re; r++) {
        float v = g_o[(size_t)r * C + c];
        s += v; s2 += v * v;
    }
    atomicAdd(&g_stats3[layer][c], s);
    atomicAdd(&g_stats3[layer][256 + c], s2);
}

// ---------------- MLP head with fused GraphNorm+LeakyReLU on input ----------------
__global__ __launch_bounds__(128) void mlp_k(const float* __restrict__ mW0, const float* __restrict__ mb0,
                                             const float* __restrict__ mW1, const float* __restrict__ mb1,
                                             const float* __restrict__ mW2, const float* __restrict__ mb2,
                                             const float* __restrict__ gw, const float* __restrict__ gb,
                                             const float* __restrict__ ga,
                                             float* __restrict__ out) {
    __shared__ float w0[64 * 32], w1[32 * 16], w2[16 * 2], bb0[32], bb1[16], bb2[2];
    __shared__ float s_scale[64], s_shift[64];
    int t = threadIdx.x;
    for (int i = t; i < 64 * 32; i += blockDim.x) w0[i] = mW0[i];
    for (int i = t; i < 32 * 16; i += blockDim.x) w1[i] = mW1[i];
    for (int i = t; i < 16 * 2;  i += blockDim.x) w2[i] = mW2[i];
    if (t < 32) bb0[t] = mb0[t];
    if (t < 16) bb1[t] = mb1[t];
    if (t < 2)  bb2[t] = mb2[t];
    if (t < 64) {
        const float* gs = g_stats3[2];
        float mu  = gs[t] * (1.f / NN);
        float ex2 = gs[256 + t] * (1.f / NN);
        float a = ga[t];
        float var = ex2 - 2.f * a * mu * mu + a * a * mu * mu;
        float sc = gw[t] * rsqrtf(var + EPSN);
        s_scale[t] = sc;
        s_shift[t] = gb[t] - a * mu * sc;
    }
    __syncthreads();
    int n = blockIdx.x * blockDim.x + t;
    if (n >= NN) return;
    float in[64];
#pragma unroll
    for (int k = 0; k < 64; k++)
        in[k] = lrelu_act(s_scale[k] * g_o[(size_t)n * 64 + k] + s_shift[k]);
    float h1[32];
#pragma unroll
    for (int j = 0; j < 32; j++) {
        float s = bb0[j];
#pragma unroll
        for (int k = 0; k < 64; k++) s += in[k] * w0[k * 32 + j];
        h1[j] = fmaxf(s, 0.f);
    }
    float h2[16];
#pragma unroll
    for (int j = 0; j < 16; j++) {
        float s = bb1[j];
#pragma unroll
        for (int k = 0; k < 32; k++) s += h1[k] * w1[k * 16 + j];
        h2[j] = fmaxf(s, 0.f);
    }
    float o0 = bb2[0], o1 = bb2[1];
#pragma unroll
    for (int k = 0; k < 16; k++) { o0 += h2[k] * w2[k * 2]; o1 += h2[k] * w2[k * 2 + 1]; }
    out[(size_t)n * 2]     = o0;
    out[(size_t)n * 2 + 1] = o1;
}

// ---------------- launch ----------------
extern "C" void kernel_launch(void* const* d_in, const int* in_sizes, int n_in,
                              void* d_out, int out_size) {
    const float* x  = (const float*)d_in[0];
    const int*   ei = (const int*)d_in[1];
    const float* W[3]  = {(const float*)d_in[2],  (const float*)d_in[9],  (const float*)d_in[16]};
    const float* As[3] = {(const float*)d_in[3],  (const float*)d_in[10], (const float*)d_in[17]};
    const float* Ad[3] = {(const float*)d_in[4],  (const float*)d_in[11], (const float*)d_in[18]};
    const float* Bb[3] = {(const float*)d_in[5],  (const float*)d_in[12], (const float*)d_in[19]};
    const float* Gw[3] = {(const float*)d_in[6],  (const float*)d_in[13], (const float*)d_in[20]};
    const float* Gb[3] = {(const float*)d_in[7],  (const float*)d_in[14], (const float*)d_in[21]};
    const float* Ga[3] = {(const float*)d_in[8],  (const float*)d_in[15], (const float*)d_in[22]};
    const float* mW0 = (const float*)d_in[23];
    const float* mb0 = (const float*)d_in[24];
    const float* mW1 = (const float*)d_in[25];
    const float* mb1 = (const float*)d_in[26];
    const float* mW2 = (const float*)d_in[27];
    const float* mb2 = (const float*)d_in[28];

    void* p_o = nullptr;
    cudaGetSymbolAddress(&p_o, g_o);

    // CSR build + stats zeroing (parallel scan)
    reset_build_k<<<NBLK, 256>>>();
    hist_k<<<(ET + 255) / 256, 256>>>(ei);
    scan1_k<<<NBLK, 256>>>();
    scan2_k<<<1, 256>>>();
    scan3_k<<<NBLK, 256>>>();
    fill_k<<<(ET + 255) / 256, 256>>>(ei);

    const float* cur_in = x;
    for (int l = 0; l < 3; l++) {
        convw_k<<<256, 256>>>(W[l]);
        dim3 gg((NN + 127) / 128, 2);
        int pn = (l > 0) ? (l - 1) : 0;
        gemm_k<<<gg, 256>>>(cur_in, l - 1, Gw[pn], Gb[pn], Ga[pn], As[l], Ad[l]);
        agg_k<<<(NN * 32 + 255) / 256, 256>>>(Bb[l], (l < 2) ? 1 : 0);
        int C = (l < 2) ? 256 : 64;
        stats_k<<<(NN + 127) / 128, C>>>(C, l);
        cur_in = (const float*)p_o;
    }
    mlp_k<<<(NN + 127) / 128, 128>>>(mW0, mb0, mW1, mb1, mW2, mb2,
                                     Gw[2], Gb[2], Ga[2], (float*)d_out);
}

// round 14
// speedup vs baseline: 1.2878x; 1.0210x over previous
#include <cuda_runtime.h>
#include <cuda_bf16.h>
#include <cuda_fp16.h>
#include <stdint.h>
#include <string.h>
#include <math.h>

#define NN 50000
#define EE 800000
#define ET (EE + NN)
#define HC 256
#define NEG_ATT 0.2f
#define NEG_ACT 0.01f
#define EPSN 1e-5f
#define NBLK 196            // ceil(NN/256)

// ---------------- scratch ----------------
__device__ __align__(16) __half2 g_hh[NN * 128];       // h in fp16 (128 half2 per row)
__device__ __align__(16) float g_o[NN * HC];           // aggregate output (raw, pre-norm)
__device__ __align__(16) float g_s[NN * 4];
__device__ __align__(16) float g_d[NN * 4];
__device__ __align__(16) __nv_bfloat16 g_wh3[3][HC * HC];  // W^T bf16 hi, per layer
__device__ __align__(16) __nv_bfloat16 g_wl3[3][HC * HC];  // W^T bf16 lo, per layer
__device__ int   g_deg[NN + 1];
__device__ int   g_off[NN + 1];
__device__ int   g_cur[NN];
__device__ int   g_csr[ET];
__device__ int   g_bsum[NBLK];
__device__ int   g_boff[NBLK];
__device__ float g_stats3[3][512];                     // per layer: [0:256) sum, [256:512) sumsq

__device__ __forceinline__ uint32_t smem_u32(const void* p) {
    uint32_t a;
    asm("{ .reg .u64 t; cvta.to.shared.u64 t, %1; cvt.u32.u64 %0, t; }" : "=r"(a) : "l"(p));
    return a;
}
__device__ __forceinline__ uint32_t bf2(float x, float y) {
    __nv_bfloat162 t = __floats2bfloat162_rn(x, y);
    uint32_t r; memcpy(&r, &t, 4); return r;
}
__device__ __forceinline__ void ldm4(uint32_t& r0, uint32_t& r1, uint32_t& r2, uint32_t& r3, uint32_t a) {
    asm volatile("ldmatrix.sync.aligned.m8n8.x4.shared.b16 {%0,%1,%2,%3}, [%4];"
                 : "=r"(r0), "=r"(r1), "=r"(r2), "=r"(r3) : "r"(a));
}
__device__ __forceinline__ void mma16816(float* c, const uint32_t* a, const uint32_t* b) {
    asm volatile("mma.sync.aligned.m16n8k16.row.col.f32.bf16.bf16.f32 "
                 "{%0,%1,%2,%3}, {%4,%5,%6,%7}, {%8,%9}, {%0,%1,%2,%3};"
                 : "+f"(c[0]), "+f"(c[1]), "+f"(c[2]), "+f"(c[3])
                 : "r"(a[0]), "r"(a[1]), "r"(a[2]), "r"(a[3]), "r"(b[0]), "r"(b[1]));
}
__device__ __forceinline__ float lrelu_act(float v) { return v > 0.f ? v : NEG_ACT * v; }
__device__ __forceinline__ float lrelu_att(float v) { return v > 0.f ? v : NEG_ATT * v; }

// ---------------- CSR build (+ per-layer stats zeroing) ----------------
__global__ void reset_build_k() {
    int i = blockIdx.x * blockDim.x + threadIdx.x;
    if (i < NN) { g_deg[i] = 0; g_cur[i] = 0; }
    if (i < 1536) ((float*)g_stats3)[i] = 0.f;
}
__global__ void hist_k(const int* __restrict__ ei) {
    int i = blockIdx.x * blockDim.x + threadIdx.x;
    if (i >= ET) return;
    int dv = (i < EE) ? ei[EE + i] : (i - EE);
    atomicAdd(&g_deg[dv], 1);
}
// parallel scan: block sums -> tiny scan -> per-block scan+apply
__global__ void scan1_k() {
    __shared__ int sh[256];
    int i = blockIdx.x * 256 + threadIdx.x;
    int v = (i < NN) ? g_deg[i] : 0;
    sh[threadIdx.x] = v;
    __syncthreads();
    for (int d = 128; d; d >>= 1) {
        if (threadIdx.x < d) sh[threadIdx.x] += sh[threadIdx.x + d];
        __syncthreads();
    }
    if (threadIdx.x == 0) g_bsum[blockIdx.x] = sh[0];
}
__global__ void scan2_k() {
    __shared__ int sh[256];
    int t = threadIdx.x;
    sh[t] = (t < NBLK) ? g_bsum[t] : 0;
    __syncthreads();
    for (int d = 1; d < 256; d <<= 1) {
        int v = (t >= d) ? sh[t - d] : 0;
        __syncthreads();
        sh[t] += v;
        __syncthreads();
    }
    if (t < NBLK) g_boff[t] = (t > 0) ? sh[t - 1] : 0;
    if (t == 255) g_off[NN] = sh[255];
}
__global__ void scan3_k() {
    __shared__ int sh[256];
    int i = blockIdx.x * 256 + threadIdx.x;
    int t = threadIdx.x;
    int v = (i < NN) ? g_deg[i] : 0;
    sh[t] = v;
    __syncthreads();
    for (int d = 1; d < 256; d <<= 1) {
        int u = (t >= d) ? sh[t - d] : 0;
        __syncthreads();
        sh[t] += u;
        __syncthreads();
    }
    if (i < NN) g_off[i] = g_boff[blockIdx.x] + sh[t] - v;   // exclusive
}
__global__ void fill_k(const int* __restrict__ ei) {
    int i = blockIdx.x * blockDim.x + threadIdx.x;
    if (i >= ET) return;
    int sv, dv;
    if (i < EE) { sv = ei[i]; dv = ei[EE + i]; }
    else        { sv = dv = i - EE; }
    int p = g_off[dv] + atomicAdd(&g_cur[dv], 1);
    g_csr[p] = sv;
}

// ---------------- W transpose + bf16 hi/lo split, all 3 layers ----------------
__global__ void convw3_k(const float* __restrict__ W0, const float* __restrict__ W1,
                         const float* __restrict__ W2) {
    int i = blockIdx.x * 256 + threadIdx.x;      // 0 .. 3*65536
    int l = i >> 16;
    int j = i & 65535;
    int n = j >> 8, k = j & 255;
    const float* W = (l == 0) ? W0 : (l == 1) ? W1 : W2;
    float v = W[k * 256 + n];
    __nv_bfloat16 h = __float2bfloat16(v);
    float lo = v - __bfloat162float(h);
    g_wh3[l][n * 256 + k] = h;
    g_wl3[l][n * 256 + k] = __float2bfloat16(lo);
}

// ---------------- HMMA GEMM (R13 champion; W from per-layer buffer) ----------------
__global__ __launch_bounds__(256, 2) void gemm_k(const float* __restrict__ A, int wlayer,
                                                 int norm_layer,
                                                 const float* __restrict__ gw,
                                                 const float* __restrict__ gb,
                                                 const float* __restrict__ ga,
                                                 const float* __restrict__ asrc,
                                                 const float* __restrict__ adst) {
    __shared__ __align__(16) char sm[32768];
    __shared__ float s_scale[256], s_shift[256];
    __shared__ float s_as[128], s_ad[128];
    __shared__ float s_red[128][2][2];
    const uint32_t sAh = smem_u32(sm);
    const uint32_t sAl = sAh + 8192;
    const uint32_t sBh = sAh + 16384;
    const uint32_t sBl = sAh + 24576;
    char* cAh = sm; char* cAl = sm + 8192; char* cBh = sm + 16384; char* cBl = sm + 24576;

    const __nv_bfloat16* __restrict__ wh = g_wh3[wlayer];
    const __nv_bfloat16* __restrict__ wl = g_wl3[wlayer];

    const int tid  = threadIdx.x;
    const int wid  = tid >> 5;
    const int lane = tid & 31;
    const int bm = blockIdx.x * 128;
    const int n0 = blockIdx.y * 128;
    const int m_off = (wid >> 2) * 64;
    const int n_off = (wid & 3) * 32;

    const int use_norm = (norm_layer >= 0);
    if (use_norm) {
        const float* gs = g_stats3[norm_layer];
        int c = tid;
        float mu  = gs[c] * (1.f / NN);
        float ex2 = gs[256 + c] * (1.f / NN);
        float a = ga[c];
        float var = ex2 - 2.f * a * mu * mu + a * a * mu * mu;
        float sc = gw[c] * rsqrtf(var + EPSN);
        s_scale[c] = sc;
        s_shift[c] = gb[c] - a * mu * sc;
    } else {
        s_scale[tid] = 1.f;
        s_shift[tid] = 0.f;
    }
    if (tid < 128) {
        s_as[tid] = asrc[n0 + tid];
        s_ad[tid] = adst[n0 + tid];
    }
    {
        float* z = &s_red[0][0][0];
        z[tid] = 0.f;
        z[tid + 256] = 0.f;
    }
    __syncthreads();

    float acc[4][4][4];
#pragma unroll
    for (int i = 0; i < 4; i++)
#pragma unroll
        for (int j = 0; j < 4; j++)
#pragma unroll
            for (int r = 0; r < 4; r++) acc[i][j][r] = 0.f;

    for (int c = 0; c < 8; c++) {
        const int k0 = c * 32;
#pragma unroll
        for (int it = 0; it < 2; it++) {
            int slot = tid + it * 256;
            int row = slot >> 2, cc = slot & 3;
            float4 v0 = make_float4(0.f, 0.f, 0.f, 0.f), v1 = v0;
            if (bm + row < NN) {
                const float* p = A + (size_t)(bm + row) * 256 + k0 + cc * 8;
                v0 = *(const float4*)p;
                v1 = *(const float4*)(p + 4);
            }
            if (use_norm) {
                int cb = k0 + cc * 8;
                v0.x = lrelu_act(s_scale[cb + 0] * v0.x + s_shift[cb + 0]);
                v0.y = lrelu_act(s_scale[cb + 1] * v0.y + s_shift[cb + 1]);
                v0.z = lrelu_act(s_scale[cb + 2] * v0.z + s_shift[cb + 2]);
                v0.w = lrelu_act(s_scale[cb + 3] * v0.w + s_shift[cb + 3]);
                v1.x = lrelu_act(s_scale[cb + 4] * v1.x + s_shift[cb + 4]);
                v1.y = lrelu_act(s_scale[cb + 5] * v1.y + s_shift[cb + 5]);
                v1.z = lrelu_act(s_scale[cb + 6] * v1.z + s_shift[cb + 6]);
                v1.w = lrelu_act(s_scale[cb + 7] * v1.w + s_shift[cb + 7]);
            }
            uint4 hi, lo;
            hi.x = bf2(v0.x, v0.y); hi.y = bf2(v0.z, v0.w);
            hi.z = bf2(v1.x, v1.y); hi.w = bf2(v1.z, v1.w);
            __nv_bfloat162 t;
            memcpy(&t, &hi.x, 4);
            lo.x = bf2(v0.x - __bfloat162float(t.x), v0.y - __bfloat162float(t.y));
            memcpy(&t, &hi.y, 4);
            lo.y = bf2(v0.z - __bfloat162float(t.x), v0.w - __bfloat162float(t.y));
            memcpy(&t, &hi.z, 4);
            lo.z = bf2(v1.x - __bfloat162float(t.x), v1.y - __bfloat162float(t.y));
            memcpy(&t, &hi.w, 4);
            lo.w = bf2(v1.z - __bfloat162float(t.x), v1.w - __bfloat162float(t.y));
            int off = row * 64 + ((cc ^ (row & 3)) << 4);
            *(uint4*)(cAh + off) = hi;
            *(uint4*)(cAl + off) = lo;
        }
#pragma unroll
        for (int it = 0; it < 2; it++) {
            int slot = tid + it * 256;
            int row = slot >> 2, cc = slot & 3;
            size_t go = (size_t)(n0 + row) * 256 + k0 + cc * 8;
            int off = row * 64 + ((cc ^ (row & 3)) << 4);
            *(uint4*)(cBh + off) = *(const uint4*)(wh + go);
            *(uint4*)(cBl + off) = *(const uint4*)(wl + go);
        }
        __syncthreads();

#pragma unroll
        for (int kk2 = 0; kk2 < 2; kk2++) {
            uint32_t afh[4][4], afl[4][4], bfh[4][2], bfl[4][2];
#pragma unroll
            for (int mi = 0; mi < 4; mi++) {
                int row_a = m_off + mi * 16 + (lane & 15);
                int cc_a = kk2 * 2 + (lane >> 4);
                uint32_t off = (uint32_t)(row_a * 64 + ((cc_a ^ (row_a & 3)) << 4));
                ldm4(afh[mi][0], afh[mi][1], afh[mi][2], afh[mi][3], sAh + off);
                ldm4(afl[mi][0], afl[mi][1], afl[mi][2], afl[mi][3], sAl + off);
            }
#pragma unroll
            for (int p = 0; p < 2; p++) {
                int gq = lane >> 3;
                int row_b = n_off + p * 16 + ((gq >> 1) << 3) + (lane & 7);
                int cc_b = kk2 * 2 + (gq & 1);
                uint32_t off = (uint32_t)(row_b * 64 + ((cc_b ^ (row_b & 3)) << 4));
                ldm4(bfh[2 * p][0], bfh[2 * p][1], bfh[2 * p + 1][0], bfh[2 * p + 1][1], sBh + off);
                ldm4(bfl[2 * p][0], bfl[2 * p][1], bfl[2 * p + 1][0], bfl[2 * p + 1][1], sBl + off);
            }
#pragma unroll
            for (int mi = 0; mi < 4; mi++)
#pragma unroll
                for (int nj = 0; nj < 4; nj++) {
                    mma16816(acc[mi][nj], afh[mi], bfh[nj]);
                    mma16816(acc[mi][nj], afh[mi], bfl[nj]);
                    mma16816(acc[mi][nj], afl[mi], bfh[nj]);
                }
        }
        __syncthreads();
    }

    // ---- epilogue: fp16 store + fused s/d (fp32 acc) ----
    const int hl = n_off >> 6;
#pragma unroll
    for (int mi = 0; mi < 4; mi++) {
        int r0 = m_off + mi * 16 + (lane >> 2);
        int m_g = bm + r0;
        float sS0 = 0.f, sS1 = 0.f, sD0 = 0.f, sD1 = 0.f;
#pragma unroll
        for (int nj = 0; nj < 4; nj++) {
            int cl = n_off + nj * 8 + (lane & 3) * 2;
            int n_g = n0 + cl;
            float a0 = s_as[cl], a1 = s_as[cl + 1];
            float d0 = s_ad[cl], d1 = s_ad[cl + 1];
            sS0 += acc[mi][nj][0] * a0 + acc[mi][nj][1] * a1;
            sD0 += acc[mi][nj][0] * d0 + acc[mi][nj][1] * d1;
            sS1 += acc[mi][nj][2] * a0 + acc[mi][nj][3] * a1;
            sD1 += acc[mi][nj][2] * d0 + acc[mi][nj][3] * d1;
            if (m_g < NN)
                g_hh[(size_t)m_g * 128 + (n_g >> 1)] = __floats2half2_rn(acc[mi][nj][0], acc[mi][nj][1]);
            if (m_g + 8 < NN)
                g_hh[(size_t)(m_g + 8) * 128 + (n_g >> 1)] = __floats2half2_rn(acc[mi][nj][2], acc[mi][nj][3]);
        }
#pragma unroll
        for (int o = 1; o < 4; o <<= 1) {
            sS0 += __shfl_xor_sync(0xffffffffu, sS0, o);
            sS1 += __shfl_xor_sync(0xffffffffu, sS1, o);
            sD0 += __shfl_xor_sync(0xffffffffu, sD0, o);
            sD1 += __shfl_xor_sync(0xffffffffu, sD1, o);
        }
        if ((lane & 3) == 0) {
            atomicAdd(&s_red[r0][hl][0], sS0);
            atomicAdd(&s_red[r0][hl][1], sD0);
            atomicAdd(&s_red[r0 + 8][hl][0], sS1);
            atomicAdd(&s_red[r0 + 8][hl][1], sD1);
        }
    }
    __syncthreads();
    {
        const int hbase = (n0 >> 6);
        int i = tid;
        int row = i >> 1, h2 = i & 1;
        if (bm + row < NN) {
            g_s[(size_t)(bm + row) * 4 + hbase + h2] = s_red[row][h2][0];
            g_d[(size_t)(bm + row) * 4 + hbase + h2] = s_red[row][h2][1];
        }
    }
}

// ---------------- GAT aggregation: warp per dst, blocked channel layout ----------------
__global__ void agg_k(const float* __restrict__ bias, int concat) {
    int w = (blockIdx.x * blockDim.x + threadIdx.x) >> 5;
    int lane = threadIdx.x & 31;
    if (w >= NN) return;

    const int mh = lane >> 3;
    float dhm = g_d[w * 4 + mh];
    int jb = g_off[w], je = g_off[w + 1];

    float acc[8] = {0.f, 0.f, 0.f, 0.f, 0.f, 0.f, 0.f, 0.f};
    float den = 0.f;
    for (int j = jb; j < je; j++) {
        int sr = g_csr[j];
        float e = lrelu_att(g_s[sr * 4 + mh] + dhm);
        float wv = __expf(e);
        den += wv;
        uint4 hv = *((const uint4*)(g_hh + (size_t)sr * 128) + lane);
        float2 f0 = __half22float2(*(__half2*)&hv.x);
        float2 f1 = __half22float2(*(__half2*)&hv.y);
        float2 f2 = __half22float2(*(__half2*)&hv.z);
        float2 f3 = __half22float2(*(__half2*)&hv.w);
        acc[0] += wv * f0.x; acc[1] += wv * f0.y;
        acc[2] += wv * f1.x; acc[3] += wv * f1.y;
        acc[4] += wv * f2.x; acc[5] += wv * f2.y;
        acc[6] += wv * f3.x; acc[7] += wv * f3.y;
    }
    float invd = 1.f / den;

    if (concat) {
        int c0 = 8 * lane;
        float4 o0 = make_float4(acc[0] * invd + bias[c0 + 0], acc[1] * invd + bias[c0 + 1],
                                acc[2] * invd + bias[c0 + 2], acc[3] * invd + bias[c0 + 3]);
        float4 o1 = make_float4(acc[4] * invd + bias[c0 + 4], acc[5] * invd + bias[c0 + 5],
                                acc[6] * invd + bias[c0 + 6], acc[7] * invd + bias[c0 + 7]);
        *(float4*)(g_o + (size_t)w * 256 + c0)     = o0;
        *(float4*)(g_o + (size_t)w * 256 + c0 + 4) = o1;
    } else {
        float v[8];
#pragma unroll
        for (int i = 0; i < 8; i++) {
            float r = acc[i] * invd;
            r += __shfl_xor_sync(0xffffffffu, r, 8);
            r += __shfl_xor_sync(0xffffffffu, r, 16);
            v[i] = 0.25f * r;
        }
        if (lane < 8) {
            int cc = 8 * lane;
            float4 o0 = make_float4(v[0] + bias[cc + 0], v[1] + bias[cc + 1],
                                    v[2] + bias[cc + 2], v[3] + bias[cc + 3]);
            float4 o1 = make_float4(v[4] + bias[cc + 4], v[5] + bias[cc + 5],
                                    v[6] + bias[cc + 6], v[7] + bias[cc + 7]);
            *(float4*)(g_o + (size_t)w * 64 + cc)     = o0;
            *(float4*)(g_o + (size_t)w * 64 + cc + 4) = o1;
        }
    }
}

// ---------------- GraphNorm stats (per-layer buffer) ----------------
__global__ void stats_k(int C, int layer) {
    int c = threadIdx.x;
    int r0 = blockIdx.x * 128;
    int re = min(r0 + 128, NN);
    float s = 0.f, s2 = 0.f;
    for (int r = r0; r < re; r++) {
        float v = g_o[(size_t)r * C + c];
        s += v; s2 += v * v;
    }
    atomicAdd(&g_stats3[layer][c], s);
    atomicAdd(&g_stats3[layer][256 + c], s2);
}

// ---------------- MLP head with fused GraphNorm+LeakyReLU on input ----------------
__global__ __launch_bounds__(128) void mlp_k(const float* __restrict__ mW0, const float* __restrict__ mb0,
                                             const float* __restrict__ mW1, const float* __restrict__ mb1,
                                             const float* __restrict__ mW2, const float* __restrict__ mb2,
                                             const float* __restrict__ gw, const float* __restrict__ gb,
                                             const float* __restrict__ ga,
                                             float* __restrict__ out) {
    __shared__ float w0[64 * 32], w1[32 * 16], w2[16 * 2], bb0[32], bb1[16], bb2[2];
    __shared__ float s_scale[64], s_shift[64];
    int t = threadIdx.x;
    for (int i = t; i < 64 * 32; i += blockDim.x) w0[i] = mW0[i];
    for (int i = t; i < 32 * 16; i += blockDim.x) w1[i] = mW1[i];
    for (int i = t; i < 16 * 2;  i += blockDim.x) w2[i] = mW2[i];
    if (t < 32) bb0[t] = mb0[t];
    if (t < 16) bb1[t] = mb1[t];
    if (t < 2)  bb2[t] = mb2[t];
    if (t < 64) {
        const float* gs = g_stats3[2];
        float mu  = gs[t] * (1.f / NN);
        float ex2 = gs[256 + t] * (1.f / NN);
        float a = ga[t];
        float var = ex2 - 2.f * a * mu * mu + a * a * mu * mu;
        float sc = gw[t] * rsqrtf(var + EPSN);
        s_scale[t] = sc;
        s_shift[t] = gb[t] - a * mu * sc;
    }
    __syncthreads();
    int n = blockIdx.x * blockDim.x + t;
    if (n >= NN) return;
    float in[64];
#pragma unroll
    for (int k = 0; k < 64; k++)
        in[k] = lrelu_act(s_scale[k] * g_o[(size_t)n * 64 + k] + s_shift[k]);
    float h1[32];
#pragma unroll
    for (int j = 0; j < 32; j++) {
        float s = bb0[j];
#pragma unroll
        for (int k = 0; k < 64; k++) s += in[k] * w0[k * 32 + j];
        h1[j] = fmaxf(s, 0.f);
    }
    float h2[16];
#pragma unroll
    for (int j = 0; j < 16; j++) {
        float s = bb1[j];
#pragma unroll
        for (int k = 0; k < 32; k++) s += h1[k] * w1[k * 16 + j];
        h2[j] = fmaxf(s, 0.f);
    }
    float o0 = bb2[0], o1 = bb2[1];
#pragma unroll
    for (int k = 0; k < 16; k++) { o0 += h2[k] * w2[k * 2]; o1 += h2[k] * w2[k * 2 + 1]; }
    out[(size_t)n * 2]     = o0;
    out[(size_t)n * 2 + 1] = o1;
}

// ---------------- launch ----------------
extern "C" void kernel_launch(void* const* d_in, const int* in_sizes, int n_in,
                              void* d_out, int out_size) {
    const float* x  = (const float*)d_in[0];
    const int*   ei = (const int*)d_in[1];
    const float* W[3]  = {(const float*)d_in[2],  (const float*)d_in[9],  (const float*)d_in[16]};
    const float* As[3] = {(const float*)d_in[3],  (const float*)d_in[10], (const float*)d_in[17]};
    const float* Ad[3] = {(const float*)d_in[4],  (const float*)d_in[11], (const float*)d_in[18]};
    const float* Bb[3] = {(const float*)d_in[5],  (const float*)d_in[12], (const float*)d_in[19]};
    const float* Gw[3] = {(const float*)d_in[6],  (const float*)d_in[13], (const float*)d_in[20]};
    const float* Gb[3] = {(const float*)d_in[7],  (const float*)d_in[14], (const float*)d_in[21]};
    const float* Ga[3] = {(const float*)d_in[8],  (const float*)d_in[15], (const float*)d_in[22]};
    const float* mW0 = (const float*)d_in[23];
    const float* mb0 = (const float*)d_in[24];
    const float* mW1 = (const float*)d_in[25];
    const float* mb1 = (const float*)d_in[26];
    const float* mW2 = (const float*)d_in[27];
    const float* mb2 = (const float*)d_in[28];

    void* p_o = nullptr;
    cudaGetSymbolAddress(&p_o, g_o);

    // Fork a side stream for the CSR build so it overlaps convw3 + gemm0.
    // (Streams/events are intentionally not destroyed: kernel_launch runs only a
    //  handful of times, and destroying a forked stream mid-capture is invalid.)
    cudaStream_t s2;
    cudaEvent_t evFork, evJoin;
    cudaStreamCreateWithFlags(&s2, cudaStreamNonBlocking);
    cudaEventCreateWithFlags(&evFork, cudaEventDisableTiming);
    cudaEventCreateWithFlags(&evJoin, cudaEventDisableTiming);

    cudaEventRecord(evFork, 0);
    cudaStreamWaitEvent(s2, evFork, 0);

    // CSR build + stats zeroing on the side stream
    reset_build_k<<<NBLK, 256, 0, s2>>>();
    hist_k<<<(ET + 255) / 256, 256, 0, s2>>>(ei);
    scan1_k<<<NBLK, 256, 0, s2>>>();
    scan2_k<<<1, 256, 0, s2>>>();
    scan3_k<<<NBLK, 256, 0, s2>>>();
    fill_k<<<(ET + 255) / 256, 256, 0, s2>>>(ei);
    cudaEventRecord(evJoin, s2);

    // Main stream: weight conversion + layer-0 GEMM (independent of CSR)
    convw3_k<<<768, 256>>>(W[0], W[1], W[2]);
    gemm_k<<<dim3((NN + 127) / 128, 2), 256>>>(x, 0, -1, Gw[0], Gb[0], Ga[0], As[0], Ad[0]);

    // Join: agg0 needs the CSR (and reset stats)
    cudaStreamWaitEvent(0, evJoin, 0);

    const float* cur_in = (const float*)p_o;
    for (int l = 0; l < 3; l++) {
        if (l > 0) {
            gemm_k<<<dim3((NN + 127) / 128, 2), 256>>>(cur_in, l, l - 1,
                                                       Gw[l - 1], Gb[l - 1], Ga[l - 1],
                                                       As[l], Ad[l]);
        }
        agg_k<<<(NN * 32 + 255) / 256, 256>>>(Bb[l], (l < 2) ? 1 : 0);
        int C = (l < 2) ? 256 : 64;
        stats_k<<<(NN + 127) / 128, C>>>(C, l);
    }
    mlp_k<<<(NN + 127) / 128, 128>>>(mW0, mb0, mW1, mb1, mW2, mb2,
                                     Gw[2], Gb[2], Ga[2], (float*)d_out);
}

// round 16
// speedup vs baseline: 1.4100x; 1.0949x over previous
#include <cuda_runtime.h>
#include <cuda_bf16.h>
#include <cuda_fp16.h>
#include <stdint.h>
#include <string.h>
#include <math.h>

#define NN 50000
#define EE 800000
#define ET (EE + NN)
#define HC 256
#define NEG_ATT 0.2f
#define NEG_ACT 0.01f
#define EPSN 1e-5f
#define NBLK 196            // ceil(NN/256)

// ---------------- scratch ----------------
__device__ __align__(16) __half2 g_hh[NN * 128];       // h in fp16 (128 half2 per row)
__device__ __align__(16) float g_o[NN * HC];           // aggregate output (raw, pre-norm)
__device__ __align__(16) float g_s[NN * 4];
__device__ __align__(16) float g_d[NN * 4];
__device__ __align__(16) __half g_wh3[3][HC * HC];     // W^T fp16 hi, per layer
__device__ __align__(16) __half g_wl3[3][HC * HC];     // W^T fp16 lo (residual), per layer
__device__ int   g_deg[NN + 1];
__device__ int   g_off[NN + 1];
__device__ int   g_cur[NN];
__device__ int   g_csr[ET];
__device__ int   g_bsum[NBLK];
__device__ int   g_boff[NBLK];
__device__ float g_stats3[3][512];                     // per layer: [0:256) sum, [256:512) sumsq

__device__ __forceinline__ uint32_t smem_u32(const void* p) {
    uint32_t a;
    asm("{ .reg .u64 t; cvta.to.shared.u64 t, %1; cvt.u32.u64 %0, t; }" : "=r"(a) : "l"(p));
    return a;
}
__device__ __forceinline__ uint32_t hf2(float x, float y) {
    __half2 t = __floats2half2_rn(x, y);
    uint32_t r; memcpy(&r, &t, 4); return r;
}
__device__ __forceinline__ void ldm4(uint32_t& r0, uint32_t& r1, uint32_t& r2, uint32_t& r3, uint32_t a) {
    asm volatile("ldmatrix.sync.aligned.m8n8.x4.shared.b16 {%0,%1,%2,%3}, [%4];"
                 : "=r"(r0), "=r"(r1), "=r"(r2), "=r"(r3) : "r"(a));
}
__device__ __forceinline__ void mma16816h(float* c, const uint32_t* a, const uint32_t* b) {
    asm volatile("mma.sync.aligned.m16n8k16.row.col.f32.f16.f16.f32 "
                 "{%0,%1,%2,%3}, {%4,%5,%6,%7}, {%8,%9}, {%0,%1,%2,%3};"
                 : "+f"(c[0]), "+f"(c[1]), "+f"(c[2]), "+f"(c[3])
                 : "r"(a[0]), "r"(a[1]), "r"(a[2]), "r"(a[3]), "r"(b[0]), "r"(b[1]));
}
__device__ __forceinline__ float lrelu_act(float v) { return v > 0.f ? v : NEG_ACT * v; }
__device__ __forceinline__ float lrelu_att(float v) { return v > 0.f ? v : NEG_ATT * v; }

// ---------------- CSR build (+ per-layer stats zeroing) ----------------
__global__ void reset_build_k() {
    int i = blockIdx.x * blockDim.x + threadIdx.x;
    if (i < NN) { g_deg[i] = 0; g_cur[i] = 0; }
    if (i < 1536) ((float*)g_stats3)[i] = 0.f;
}
__global__ void hist_k(const int* __restrict__ ei) {
    int i = blockIdx.x * blockDim.x + threadIdx.x;
    if (i >= ET) return;
    int dv = (i < EE) ? ei[EE + i] : (i - EE);
    atomicAdd(&g_deg[dv], 1);
}
__global__ void scan1_k() {
    __shared__ int sh[256];
    int i = blockIdx.x * 256 + threadIdx.x;
    int v = (i < NN) ? g_deg[i] : 0;
    sh[threadIdx.x] = v;
    __syncthreads();
    for (int d = 128; d; d >>= 1) {
        if (threadIdx.x < d) sh[threadIdx.x] += sh[threadIdx.x + d];
        __syncthreads();
    }
    if (threadIdx.x == 0) g_bsum[blockIdx.x] = sh[0];
}
__global__ void scan2_k() {
    __shared__ int sh[256];
    int t = threadIdx.x;
    sh[t] = (t < NBLK) ? g_bsum[t] : 0;
    __syncthreads();
    for (int d = 1; d < 256; d <<= 1) {
        int v = (t >= d) ? sh[t - d] : 0;
        __syncthreads();
        sh[t] += v;
        __syncthreads();
    }
    if (t < NBLK) g_boff[t] = (t > 0) ? sh[t - 1] : 0;
    if (t == 255) g_off[NN] = sh[255];
}
__global__ void scan3_k() {
    __shared__ int sh[256];
    int i = blockIdx.x * 256 + threadIdx.x;
    int t = threadIdx.x;
    int v = (i < NN) ? g_deg[i] : 0;
    sh[t] = v;
    __syncthreads();
    for (int d = 1; d < 256; d <<= 1) {
        int u = (t >= d) ? sh[t - d] : 0;
        __syncthreads();
        sh[t] += u;
        __syncthreads();
    }
    if (i < NN) g_off[i] = g_boff[blockIdx.x] + sh[t] - v;   // exclusive
}
__global__ void fill_k(const int* __restrict__ ei) {
    int i = blockIdx.x * blockDim.x + threadIdx.x;
    if (i >= ET) return;
    int sv, dv;
    if (i < EE) { sv = ei[i]; dv = ei[EE + i]; }
    else        { sv = dv = i - EE; }
    int p = g_off[dv] + atomicAdd(&g_cur[dv], 1);
    g_csr[p] = sv;
}

// ---------------- W transpose + fp16 hi/lo split, all 3 layers ----------------
__global__ void convw3_k(const float* __restrict__ W0, const float* __restrict__ W1,
                         const float* __restrict__ W2) {
    int i = blockIdx.x * 256 + threadIdx.x;      // 0 .. 3*65536
    int l = i >> 16;
    int j = i & 65535;
    int n = j >> 8, k = j & 255;
    const float* W = (l == 0) ? W0 : (l == 1) ? W1 : W2;
    float v = W[k * 256 + n];
    __half h = __float2half_rn(v);
    float lo = v - __half2float(h);
    g_wh3[l][n * 256 + k] = h;
    g_wl3[l][n * 256 + k] = __float2half_rn(lo);
}

// ---------------- HMMA GEMM: A fp16-single, W fp16 hi/lo => 2 MMAs per tile ----------------
__global__ __launch_bounds__(256, 2) void gemm_k(const float* __restrict__ A, int wlayer,
                                                 int norm_layer,
                                                 const float* __restrict__ gw,
                                                 const float* __restrict__ gb,
                                                 const float* __restrict__ ga,
                                                 const float* __restrict__ asrc,
                                                 const float* __restrict__ adst) {
    __shared__ __align__(16) char sm[24576];     // A 8K | Bh 8K | Bl 8K
    __shared__ float s_scale[256], s_shift[256];
    __shared__ float s_as[128], s_ad[128];
    __shared__ float s_red[128][2][2];
    const uint32_t sA  = smem_u32(sm);
    const uint32_t sBh = sA + 8192;
    const uint32_t sBl = sA + 16384;
    char* cA = sm; char* cBh = sm + 8192; char* cBl = sm + 16384;

    const __half* __restrict__ wh = g_wh3[wlayer];
    const __half* __restrict__ wl = g_wl3[wlayer];

    const int tid  = threadIdx.x;
    const int wid  = tid >> 5;
    const int lane = tid & 31;
    const int bm = blockIdx.x * 128;
    const int n0 = blockIdx.y * 128;
    const int m_off = (wid >> 2) * 64;
    const int n_off = (wid & 3) * 32;

    const int use_norm = (norm_layer >= 0);
    if (use_norm) {
        const float* gs = g_stats3[norm_layer];
        int c = tid;
        float mu  = gs[c] * (1.f / NN);
        float ex2 = gs[256 + c] * (1.f / NN);
        float a = ga[c];
        float var = ex2 - 2.f * a * mu * mu + a * a * mu * mu;
        float sc = gw[c] * rsqrtf(var + EPSN);
        s_scale[c] = sc;
        s_shift[c] = gb[c] - a * mu * sc;
    } else {
        s_scale[tid] = 1.f;
        s_shift[tid] = 0.f;
    }
    if (tid < 128) {
        s_as[tid] = asrc[n0 + tid];
        s_ad[tid] = adst[n0 + tid];
    }
    {
        float* z = &s_red[0][0][0];
        z[tid] = 0.f;
        z[tid + 256] = 0.f;
    }
    __syncthreads();

    float acc[4][4][4];
#pragma unroll
    for (int i = 0; i < 4; i++)
#pragma unroll
        for (int j = 0; j < 4; j++)
#pragma unroll
            for (int r = 0; r < 4; r++) acc[i][j][r] = 0.f;

    for (int c = 0; c < 8; c++) {
        const int k0 = c * 32;
        // ---- A chunk: LDG fp32, norm+act, fp16 single, swizzled STS ----
#pragma unroll
        for (int it = 0; it < 2; it++) {
            int slot = tid + it * 256;
            int row = slot >> 2, cc = slot & 3;
            float4 v0 = make_float4(0.f, 0.f, 0.f, 0.f), v1 = v0;
            if (bm + row < NN) {
                const float* p = A + (size_t)(bm + row) * 256 + k0 + cc * 8;
                v0 = *(const float4*)p;
                v1 = *(const float4*)(p + 4);
            }
            if (use_norm) {
                int cb = k0 + cc * 8;
                v0.x = lrelu_act(s_scale[cb + 0] * v0.x + s_shift[cb + 0]);
                v0.y = lrelu_act(s_scale[cb + 1] * v0.y + s_shift[cb + 1]);
                v0.z = lrelu_act(s_scale[cb + 2] * v0.z + s_shift[cb + 2]);
                v0.w = lrelu_act(s_scale[cb + 3] * v0.w + s_shift[cb + 3]);
                v1.x = lrelu_act(s_scale[cb + 4] * v1.x + s_shift[cb + 4]);
                v1.y = lrelu_act(s_scale[cb + 5] * v1.y + s_shift[cb + 5]);
                v1.z = lrelu_act(s_scale[cb + 6] * v1.z + s_shift[cb + 6]);
                v1.w = lrelu_act(s_scale[cb + 7] * v1.w + s_shift[cb + 7]);
            }
            uint4 hi;
            hi.x = hf2(v0.x, v0.y); hi.y = hf2(v0.z, v0.w);
            hi.z = hf2(v1.x, v1.y); hi.w = hf2(v1.z, v1.w);
            int off = row * 64 + ((cc ^ (row & 3)) << 4);
            *(uint4*)(cA + off) = hi;
        }
        // ---- B chunk: fp16 hi/lo from global ----
#pragma unroll
        for (int it = 0; it < 2; it++) {
            int slot = tid + it * 256;
            int row = slot >> 2, cc = slot & 3;
            size_t go = (size_t)(n0 + row) * 256 + k0 + cc * 8;
            int off = row * 64 + ((cc ^ (row & 3)) << 4);
            *(uint4*)(cBh + off) = *(const uint4*)(wh + go);
            *(uint4*)(cBl + off) = *(const uint4*)(wl + go);
        }
        __syncthreads();

#pragma unroll
        for (int kk2 = 0; kk2 < 2; kk2++) {
            uint32_t af[4][4], bfh[4][2], bfl[4][2];
#pragma unroll
            for (int mi = 0; mi < 4; mi++) {
                int row_a = m_off + mi * 16 + (lane & 15);
                int cc_a = kk2 * 2 + (lane >> 4);
                uint32_t off = (uint32_t)(row_a * 64 + ((cc_a ^ (row_a & 3)) << 4));
                ldm4(af[mi][0], af[mi][1], af[mi][2], af[mi][3], sA + off);
            }
#pragma unroll
            for (int p = 0; p < 2; p++) {
                int gq = lane >> 3;
                int row_b = n_off + p * 16 + ((gq >> 1) << 3) + (lane & 7);
                int cc_b = kk2 * 2 + (gq & 1);
                uint32_t off = (uint32_t)(row_b * 64 + ((cc_b ^ (row_b & 3)) << 4));
                ldm4(bfh[2 * p][0], bfh[2 * p][1], bfh[2 * p + 1][0], bfh[2 * p + 1][1], sBh + off);
                ldm4(bfl[2 * p][0], bfl[2 * p][1], bfl[2 * p + 1][0], bfl[2 * p + 1][1], sBl + off);
            }
#pragma unroll
            for (int mi = 0; mi < 4; mi++)
#pragma unroll
                for (int nj = 0; nj < 4; nj++) {
                    mma16816h(acc[mi][nj], af[mi], bfh[nj]);
                    mma16816h(acc[mi][nj], af[mi], bfl[nj]);
                }
        }
        __syncthreads();
    }

    // ---- epilogue: fp16 store + fused s/d (fp32 acc) ----
    const int hl = n_off >> 6;
#pragma unroll
    for (int mi = 0; mi < 4; mi++) {
        int r0 = m_off + mi * 16 + (lane >> 2);
        int m_g = bm + r0;
        float sS0 = 0.f, sS1 = 0.f, sD0 = 0.f, sD1 = 0.f;
#pragma unroll
        for (int nj = 0; nj < 4; nj++) {
            int cl = n_off + nj * 8 + (lane & 3) * 2;
            int n_g = n0 + cl;
            float a0 = s_as[cl], a1 = s_as[cl + 1];
            float d0 = s_ad[cl], d1 = s_ad[cl + 1];
            sS0 += acc[mi][nj][0] * a0 + acc[mi][nj][1] * a1;
            sD0 += acc[mi][nj][0] * d0 + acc[mi][nj][1] * d1;
            sS1 += acc[mi][nj][2] * a0 + acc[mi][nj][3] * a1;
            sD1 += acc[mi][nj][2] * d0 + acc[mi][nj][3] * d1;
            if (m_g < NN)
                g_hh[(size_t)m_g * 128 + (n_g >> 1)] = __floats2half2_rn(acc[mi][nj][0], acc[mi][nj][1]);
            if (m_g + 8 < NN)
                g_hh[(size_t)(m_g + 8) * 128 + (n_g >> 1)] = __floats2half2_rn(acc[mi][nj][2], acc[mi][nj][3]);
        }
#pragma unroll
        for (int o = 1; o < 4; o <<= 1) {
            sS0 += __shfl_xor_sync(0xffffffffu, sS0, o);
            sS1 += __shfl_xor_sync(0xffffffffu, sS1, o);
            sD0 += __shfl_xor_sync(0xffffffffu, sD0, o);
            sD1 += __shfl_xor_sync(0xffffffffu, sD1, o);
        }
        if ((lane & 3) == 0) {
            atomicAdd(&s_red[r0][hl][0], sS0);
            atomicAdd(&s_red[r0][hl][1], sD0);
            atomicAdd(&s_red[r0 + 8][hl][0], sS1);
            atomicAdd(&s_red[r0 + 8][hl][1], sD1);
        }
    }
    __syncthreads();
    {
        const int hbase = (n0 >> 6);
        int i = tid;
        int row = i >> 1, h2 = i & 1;
        if (bm + row < NN) {
            g_s[(size_t)(bm + row) * 4 + hbase + h2] = s_red[row][h2][0];
            g_d[(size_t)(bm + row) * 4 + hbase + h2] = s_red[row][h2][1];
        }
    }
}

// ---------------- GAT aggregation: warp per dst, blocked channel layout ----------------
__global__ void agg_k(const float* __restrict__ bias, int concat) {
    int w = (blockIdx.x * blockDim.x + threadIdx.x) >> 5;
    int lane = threadIdx.x & 31;
    if (w >= NN) return;

    const int mh = lane >> 3;
    float dhm = g_d[w * 4 + mh];
    int jb = g_off[w], je = g_off[w + 1];

    float acc[8] = {0.f, 0.f, 0.f, 0.f, 0.f, 0.f, 0.f, 0.f};
    float den = 0.f;
    for (int j = jb; j < je; j++) {
        int sr = g_csr[j];
        float e = lrelu_att(g_s[sr * 4 + mh] + dhm);
        float wv = __expf(e);
        den += wv;
        uint4 hv = *((const uint4*)(g_hh + (size_t)sr * 128) + lane);
        float2 f0 = __half22float2(*(__half2*)&hv.x);
        float2 f1 = __half22float2(*(__half2*)&hv.y);
        float2 f2 = __half22float2(*(__half2*)&hv.z);
        float2 f3 = __half22float2(*(__half2*)&hv.w);
        acc[0] += wv * f0.x; acc[1] += wv * f0.y;
        acc[2] += wv * f1.x; acc[3] += wv * f1.y;
        acc[4] += wv * f2.x; acc[5] += wv * f2.y;
        acc[6] += wv * f3.x; acc[7] += wv * f3.y;
    }
    float invd = 1.f / den;

    if (concat) {
        int c0 = 8 * lane;
        float4 o0 = make_float4(acc[0] * invd + bias[c0 + 0], acc[1] * invd + bias[c0 + 1],
                                acc[2] * invd + bias[c0 + 2], acc[3] * invd + bias[c0 + 3]);
        float4 o1 = make_float4(acc[4] * invd + bias[c0 + 4], acc[5] * invd + bias[c0 + 5],
                                acc[6] * invd + bias[c0 + 6], acc[7] * invd + bias[c0 + 7]);
        *(float4*)(g_o + (size_t)w * 256 + c0)     = o0;
        *(float4*)(g_o + (size_t)w * 256 + c0 + 4) = o1;
    } else {
        float v[8];
#pragma unroll
        for (int i = 0; i < 8; i++) {
            float r = acc[i] * invd;
            r += __shfl_xor_sync(0xffffffffu, r, 8);
            r += __shfl_xor_sync(0xffffffffu, r, 16);
            v[i] = 0.25f * r;
        }
        if (lane < 8) {
            int cc = 8 * lane;
            float4 o0 = make_float4(v[0] + bias[cc + 0], v[1] + bias[cc + 1],
                                    v[2] + bias[cc + 2], v[3] + bias[cc + 3]);
            float4 o1 = make_float4(v[4] + bias[cc + 4], v[5] + bias[cc + 5],
                                    v[6] + bias[cc + 6], v[7] + bias[cc + 7]);
            *(float4*)(g_o + (size_t)w * 64 + cc)     = o0;
            *(float4*)(g_o + (size_t)w * 64 + cc + 4) = o1;
        }
    }
}

// ---------------- GraphNorm stats (per-layer buffer) ----------------
__global__ void stats_k(int C, int layer) {
    int c = threadIdx.x;
    int r0 = blockIdx.x * 128;
    int re = min(r0 + 128, NN);
    float s = 0.f, s2 = 0.f;
    for (int r = r0; r < re; r++) {
        float v = g_o[(size_t)r * C + c];
        s += v; s2 += v * v;
    }
    atomicAdd(&g_stats3[layer][c], s);
    atomicAdd(&g_stats3[layer][256 + c], s2);
}

// ---------------- MLP head with fused GraphNorm+LeakyReLU on input ----------------
__global__ __launch_bounds__(128) void mlp_k(const float* __restrict__ mW0, const float* __restrict__ mb0,
                                             const float* __restrict__ mW1, const float* __restrict__ mb1,
                                             const float* __restrict__ mW2, const float* __restrict__ mb2,
                                             const float* __restrict__ gw, const float* __restrict__ gb,
                                             const float* __restrict__ ga,
                                             float* __restrict__ out) {
    __shared__ float w0[64 * 32], w1[32 * 16], w2[16 * 2], bb0[32], bb1[16], bb2[2];
    __shared__ float s_scale[64], s_shift[64];
    int t = threadIdx.x;
    for (int i = t; i < 64 * 32; i += blockDim.x) w0[i] = mW0[i];
    for (int i = t; i < 32 * 16; i += blockDim.x) w1[i] = mW1[i];
    for (int i = t; i < 16 * 2;  i += blockDim.x) w2[i] = mW2[i];
    if (t < 32) bb0[t] = mb0[t];
    if (t < 16) bb1[t] = mb1[t];
    if (t < 2)  bb2[t] = mb2[t];
    if (t < 64) {
        const float* gs = g_stats3[2];
        float mu  = gs[t] * (1.f / NN);
        float ex2 = gs[256 + t] * (1.f / NN);
        float a = ga[t];
        float var = ex2 - 2.f * a * mu * mu + a * a * mu * mu;
        float sc = gw[t] * rsqrtf(var + EPSN);
        s_scale[t] = sc;
        s_shift[t] = gb[t] - a * mu * sc;
    }
    __syncthreads();
    int n = blockIdx.x * blockDim.x + t;
    if (n >= NN) return;
    float in[64];
#pragma unroll
    for (int k = 0; k < 64; k++)
        in[k] = lrelu_act(s_scale[k] * g_o[(size_t)n * 64 + k] + s_shift[k]);
    float h1[32];
#pragma unroll
    for (int j = 0; j < 32; j++) {
        float s = bb0[j];
#pragma unroll
        for (int k = 0; k < 64; k++) s += in[k] * w0[k * 32 + j];
        h1[j] = fmaxf(s, 0.f);
    }
    float h2[16];
#pragma unroll
    for (int j = 0; j < 16; j++) {
        float s = bb1[j];
#pragma unroll
        for (int k = 0; k < 32; k++) s += h1[k] * w1[k * 16 + j];
        h2[j] = fmaxf(s, 0.f);
    }
    float o0 = bb2[0], o1 = bb2[1];
#pragma unroll
    for (int k = 0; k < 16; k++) { o0 += h2[k] * w2[k * 2]; o1 += h2[k] * w2[k * 2 + 1]; }
    out[(size_t)n * 2]     = o0;
    out[(size_t)n * 2 + 1] = o1;
}

// ---------------- launch ----------------
extern "C" void kernel_launch(void* const* d_in, const int* in_sizes, int n_in,
                              void* d_out, int out_size) {
    const float* x  = (const float*)d_in[0];
    const int*   ei = (const int*)d_in[1];
    const float* W[3]  = {(const float*)d_in[2],  (const float*)d_in[9],  (const float*)d_in[16]};
    const float* As[3] = {(const float*)d_in[3],  (const float*)d_in[10], (const float*)d_in[17]};
    const float* Ad[3] = {(const float*)d_in[4],  (const float*)d_in[11], (const float*)d_in[18]};
    const float* Bb[3] = {(const float*)d_in[5],  (const float*)d_in[12], (const float*)d_in[19]};
    const float* Gw[3] = {(const float*)d_in[6],  (const float*)d_in[13], (const float*)d_in[20]};
    const float* Gb[3] = {(const float*)d_in[7],  (const float*)d_in[14], (const float*)d_in[21]};
    const float* Ga[3] = {(const float*)d_in[8],  (const float*)d_in[15], (const float*)d_in[22]};
    const float* mW0 = (const float*)d_in[23];
    const float* mb0 = (const float*)d_in[24];
    const float* mW1 = (const float*)d_in[25];
    const float* mb1 = (const float*)d_in[26];
    const float* mW2 = (const float*)d_in[27];
    const float* mb2 = (const float*)d_in[28];

    void* p_o = nullptr;
    cudaGetSymbolAddress(&p_o, g_o);

    // Fork a side stream for the CSR build so it overlaps convw3 + gemm0.
    cudaStream_t s2;
    cudaEvent_t evFork, evJoin;
    cudaStreamCreateWithFlags(&s2, cudaStreamNonBlocking);
    cudaEventCreateWithFlags(&evFork, cudaEventDisableTiming);
    cudaEventCreateWithFlags(&evJoin, cudaEventDisableTiming);

    cudaEventRecord(evFork, 0);
    cudaStreamWaitEvent(s2, evFork, 0);

    reset_build_k<<<NBLK, 256, 0, s2>>>();
    hist_k<<<(ET + 255) / 256, 256, 0, s2>>>(ei);
    scan1_k<<<NBLK, 256, 0, s2>>>();
    scan2_k<<<1, 256, 0, s2>>>();
    scan3_k<<<NBLK, 256, 0, s2>>>();
    fill_k<<<(ET + 255) / 256, 256, 0, s2>>>(ei);
    cudaEventRecord(evJoin, s2);

    convw3_k<<<768, 256>>>(W[0], W[1], W[2]);
    gemm_k<<<dim3((NN + 127) / 128, 2), 256>>>(x, 0, -1, Gw[0], Gb[0], Ga[0], As[0], Ad[0]);

    cudaStreamWaitEvent(0, evJoin, 0);

    const float* cur_in = (const float*)p_o;
    for (int l = 0; l < 3; l++) {
        if (l > 0) {
            gemm_k<<<dim3((NN + 127) / 128, 2), 256>>>(cur_in, l, l - 1,
                                                       Gw[l - 1], Gb[l - 1], Ga[l - 1],
                                                       As[l], Ad[l]);
        }
        agg_k<<<(NN * 32 + 255) / 256, 256>>>(Bb[l], (l < 2) ? 1 : 0);
        int C = (l < 2) ? 256 : 64;
        stats_k<<<(NN + 127) / 128, C>>>(C, l);
    }
    mlp_k<<<(NN + 127) / 128, 128>>>(mW0, mb0, mW1, mb1, mW2, mb2,
                                     Gw[2], Gb[2], Ga[2], (float*)d_out);
}